// round 6
// baseline (speedup 1.0000x reference)
#include <cuda_runtime.h>
#include <math.h>

#define VOCAB 50257
#define BATCH 512
#define SEQ   512
#define EMBED 256
#define OUTC  5
#define EV4   (EMBED / 4)   // 64 float4 per embedding row
#define PROJ_STRIDE 8       // padded floats per vocab entry (32 B aligned)

// Device scratch (mallocs forbidden). g_count zero at load, reset in-kernel
// every call -> graph-replay safe.
__device__ float        g_proj[(size_t)VOCAB * PROJ_STRIDE];  // ~1.6 MB
__device__ float        g_loss[BATCH];
__device__ unsigned int g_count;

// ---------------------------------------------------------------------------
// Kernel 1: proj[v][o] = dot(emb[v,:], W[o,:]).  Warp-per-row, dense coalesced
// streaming of the 51.5 MB table (stays L2-warm across graph replays).
// ---------------------------------------------------------------------------
__global__ __launch_bounds__(256)
void proj_kernel(const float* __restrict__ emb,
                 const float* __restrict__ W)
{
    const int tid    = threadIdx.x;
    const int lane   = tid & 31;
    const int gw     = (blockIdx.x * blockDim.x + tid) >> 5;
    const int stride = (gridDim.x * blockDim.x) >> 5;

    const float4* __restrict__ embv = (const float4*)emb;
    const float4* __restrict__ Wv   = (const float4*)W;

    // Each lane keeps its two W float4 slices per output in registers (40 regs)
    float4 w0[OUTC], w1[OUTC];
    #pragma unroll
    for (int o = 0; o < OUTC; o++) {
        w0[o] = Wv[o * EV4 + lane];
        w1[o] = Wv[o * EV4 + 32 + lane];
    }

    int row = gw;
    // Two rows per iteration: 4 coalesced LDG.128 in flight per lane
    for (; row + stride < VOCAB; row += 2 * stride) {
        const int rA = row, rB = row + stride;
        float4 a0 = embv[(long)rA * EV4 + lane];
        float4 a1 = embv[(long)rA * EV4 + 32 + lane];
        float4 b0 = embv[(long)rB * EV4 + lane];
        float4 b1 = embv[(long)rB * EV4 + 32 + lane];

        float accA[OUTC], accB[OUTC];
        #pragma unroll
        for (int o = 0; o < OUTC; o++) {
            accA[o] = a0.x * w0[o].x + a0.y * w0[o].y + a0.z * w0[o].z + a0.w * w0[o].w
                    + a1.x * w1[o].x + a1.y * w1[o].y + a1.z * w1[o].z + a1.w * w1[o].w;
            accB[o] = b0.x * w0[o].x + b0.y * w0[o].y + b0.z * w0[o].z + b0.w * w0[o].w
                    + b1.x * w1[o].x + b1.y * w1[o].y + b1.z * w1[o].z + b1.w * w1[o].w;
        }
        #pragma unroll
        for (int o = 0; o < OUTC; o++) {
            #pragma unroll
            for (int off = 16; off > 0; off >>= 1) {
                accA[o] += __shfl_down_sync(0xffffffffu, accA[o], off);
                accB[o] += __shfl_down_sync(0xffffffffu, accB[o], off);
            }
        }
        if (lane == 0) {
            float4 sA = make_float4(accA[0], accA[1], accA[2], accA[3]);
            float4 sB = make_float4(accB[0], accB[1], accB[2], accB[3]);
            *(float4*)&g_proj[(long)rA * PROJ_STRIDE] = sA;
            g_proj[(long)rA * PROJ_STRIDE + 4] = accA[4];
            *(float4*)&g_proj[(long)rB * PROJ_STRIDE] = sB;
            g_proj[(long)rB * PROJ_STRIDE + 4] = accB[4];
        }
    }
    // Tail rows
    for (; row < VOCAB; row += stride) {
        float4 a0 = embv[(long)row * EV4 + lane];
        float4 a1 = embv[(long)row * EV4 + 32 + lane];
        float acc[OUTC];
        #pragma unroll
        for (int o = 0; o < OUTC; o++) {
            acc[o] = a0.x * w0[o].x + a0.y * w0[o].y + a0.z * w0[o].z + a0.w * w0[o].w
                   + a1.x * w1[o].x + a1.y * w1[o].y + a1.z * w1[o].z + a1.w * w1[o].w;
        }
        #pragma unroll
        for (int o = 0; o < OUTC; o++) {
            #pragma unroll
            for (int off = 16; off > 0; off >>= 1)
                acc[o] += __shfl_down_sync(0xffffffffu, acc[o], off);
        }
        if (lane == 0) {
            float4 sA = make_float4(acc[0], acc[1], acc[2], acc[3]);
            *(float4*)&g_proj[(long)row * PROJ_STRIDE] = sA;
            g_proj[(long)row * PROJ_STRIDE + 4] = acc[4];
        }
    }
}

// ---------------------------------------------------------------------------
// Kernel 2: warp-per-sample ragged sum of proj rows (24 B/token), then
// softmax/NLL, then fused mean via last-block pattern.
// ---------------------------------------------------------------------------
__global__ __launch_bounds__(256)
void loss_kernel(const int*   __restrict__ input_x,
                 const int*   __restrict__ lengths,
                 const int*   __restrict__ input_y,
                 const float* __restrict__ bias,
                 float*       __restrict__ out)
{
    __shared__ float s_sum[256];
    __shared__ int   s_last;

    const int tid  = threadIdx.x;
    const int wid  = tid >> 5;
    const int lane = tid & 31;
    const int b    = blockIdx.x * 8 + wid;   // warp-per-sample, grid = 64
    const int len  = lengths[b];

    const int* xrow = input_x + b * SEQ;

    float acc[OUTC];
    #pragma unroll
    for (int o = 0; o < OUTC; o++) acc[o] = 0.f;

    int s = lane;
    // Two tokens per iteration: 4 loads in flight per lane
    for (; s + 32 < len; s += 64) {
        const int t0 = xrow[s];
        const int t1 = xrow[s + 32];
        float4 p0 = *(const float4*)&g_proj[(long)t0 * PROJ_STRIDE];
        float  q0 = g_proj[(long)t0 * PROJ_STRIDE + 4];
        float4 p1 = *(const float4*)&g_proj[(long)t1 * PROJ_STRIDE];
        float  q1 = g_proj[(long)t1 * PROJ_STRIDE + 4];
        acc[0] += p0.x + p1.x;
        acc[1] += p0.y + p1.y;
        acc[2] += p0.z + p1.z;
        acc[3] += p0.w + p1.w;
        acc[4] += q0 + q1;
    }
    if (s < len) {
        const int t0 = xrow[s];
        float4 p0 = *(const float4*)&g_proj[(long)t0 * PROJ_STRIDE];
        float  q0 = g_proj[(long)t0 * PROJ_STRIDE + 4];
        acc[0] += p0.x; acc[1] += p0.y; acc[2] += p0.z; acc[3] += p0.w;
        acc[4] += q0;
    }

    #pragma unroll
    for (int o = 0; o < OUTC; o++) {
        #pragma unroll
        for (int off = 16; off > 0; off >>= 1)
            acc[o] += __shfl_down_sync(0xffffffffu, acc[o], off);
    }

    if (lane == 0) {
        const float inv_len = 1.0f / (float)len;
        float logits[OUTC];
        float m = -INFINITY;
        #pragma unroll
        for (int o = 0; o < OUTC; o++) {
            logits[o] = acc[o] * inv_len + bias[o];
            m = fmaxf(m, logits[o]);
        }
        float se = 0.f;
        #pragma unroll
        for (int o = 0; o < OUTC; o++) se += __expf(logits[o] - m);
        const float lse = m + __logf(se);
        const int y = input_y[b];
        g_loss[b] = lse - logits[y];
    }
    __syncthreads();

    if (tid == 0) {
        __threadfence();
        s_last = (atomicAdd(&g_count, 1u) == gridDim.x - 1) ? 1 : 0;
    }
    __syncthreads();

    // Last block: mean over 512 losses
    if (s_last) {
        __threadfence();
        s_sum[tid] = g_loss[tid] + g_loss[tid + 256];
        __syncthreads();
        #pragma unroll
        for (int off = 128; off > 0; off >>= 1) {
            if (tid < off) s_sum[tid] += s_sum[tid + off];
            __syncthreads();
        }
        if (tid == 0) {
            out[0] = s_sum[0] * (1.0f / (float)BATCH);
            g_count = 0;   // reset for next replay
        }
    }
}

extern "C" void kernel_launch(void* const* d_in, const int* in_sizes, int n_in,
                              void* d_out, int out_size)
{
    const int*   input_x = (const int*)d_in[0];
    const int*   lengths = (const int*)d_in[1];
    const int*   input_y = (const int*)d_in[2];
    const float* emb     = (const float*)d_in[3];
    const float* W       = (const float*)d_in[4];
    const float* bias    = (const float*)d_in[5];
    float* out = (float*)d_out;

    proj_kernel<<<592, 256>>>(emb, W);
    loss_kernel<<<64, 256>>>(input_x, lengths, input_y, bias, out);
}

// round 7
// speedup vs baseline: 1.1215x; 1.1215x over previous
#include <cuda_runtime.h>
#include <math.h>

#define VOCAB 50257
#define BATCH 512
#define SEQ   512
#define EMBED 256
#define OUTC  5
#define EV4   (EMBED / 4)   // 64 float4 per embedding row
#define PROJ_STRIDE 8       // padded floats per vocab entry (32 B aligned)

// Device scratch (mallocs forbidden). g_count zero at load, reset in-kernel
// every call -> graph-replay safe.
__device__ float        g_proj[(size_t)VOCAB * PROJ_STRIDE];  // ~1.6 MB
__device__ float        g_loss[BATCH];
__device__ unsigned int g_count;

// ---------------------------------------------------------------------------
// Kernel 1: proj[v][o] = dot(emb[v,:], W[o,:]).  Warp-per-row, dense coalesced
// streaming of the 51.5 MB table (L2-warm across graph replays).
// ---------------------------------------------------------------------------
__global__ __launch_bounds__(256)
void proj_kernel(const float* __restrict__ emb,
                 const float* __restrict__ W)
{
    const int tid    = threadIdx.x;
    const int lane   = tid & 31;
    const int gw     = (blockIdx.x * blockDim.x + tid) >> 5;
    const int stride = (gridDim.x * blockDim.x) >> 5;

    const float4* __restrict__ embv = (const float4*)emb;
    const float4* __restrict__ Wv   = (const float4*)W;

    // Each lane holds its two W float4 slices per output (40 regs)
    float4 w0[OUTC], w1[OUTC];
    #pragma unroll
    for (int o = 0; o < OUTC; o++) {
        w0[o] = Wv[o * EV4 + lane];
        w1[o] = Wv[o * EV4 + 32 + lane];
    }

    int row = gw;
    // Two rows per iteration: 4 coalesced LDG.128 in flight per lane
    for (; row + stride < VOCAB; row += 2 * stride) {
        const int rA = row, rB = row + stride;
        float4 a0 = embv[(long)rA * EV4 + lane];
        float4 a1 = embv[(long)rA * EV4 + 32 + lane];
        float4 b0 = embv[(long)rB * EV4 + lane];
        float4 b1 = embv[(long)rB * EV4 + 32 + lane];

        float accA[OUTC], accB[OUTC];
        #pragma unroll
        for (int o = 0; o < OUTC; o++) {
            accA[o] = a0.x * w0[o].x + a0.y * w0[o].y + a0.z * w0[o].z + a0.w * w0[o].w
                    + a1.x * w1[o].x + a1.y * w1[o].y + a1.z * w1[o].z + a1.w * w1[o].w;
            accB[o] = b0.x * w0[o].x + b0.y * w0[o].y + b0.z * w0[o].z + b0.w * w0[o].w
                    + b1.x * w1[o].x + b1.y * w1[o].y + b1.z * w1[o].z + b1.w * w1[o].w;
        }
        #pragma unroll
        for (int o = 0; o < OUTC; o++) {
            #pragma unroll
            for (int off = 16; off > 0; off >>= 1) {
                accA[o] += __shfl_down_sync(0xffffffffu, accA[o], off);
                accB[o] += __shfl_down_sync(0xffffffffu, accB[o], off);
            }
        }
        if (lane == 0) {
            *(float4*)&g_proj[(long)rA * PROJ_STRIDE] =
                make_float4(accA[0], accA[1], accA[2], accA[3]);
            g_proj[(long)rA * PROJ_STRIDE + 4] = accA[4];
            *(float4*)&g_proj[(long)rB * PROJ_STRIDE] =
                make_float4(accB[0], accB[1], accB[2], accB[3]);
            g_proj[(long)rB * PROJ_STRIDE + 4] = accB[4];
        }
    }
    for (; row < VOCAB; row += stride) {
        float4 a0 = embv[(long)row * EV4 + lane];
        float4 a1 = embv[(long)row * EV4 + 32 + lane];
        float acc[OUTC];
        #pragma unroll
        for (int o = 0; o < OUTC; o++) {
            acc[o] = a0.x * w0[o].x + a0.y * w0[o].y + a0.z * w0[o].z + a0.w * w0[o].w
                   + a1.x * w1[o].x + a1.y * w1[o].y + a1.z * w1[o].z + a1.w * w1[o].w;
        }
        #pragma unroll
        for (int o = 0; o < OUTC; o++) {
            #pragma unroll
            for (int off = 16; off > 0; off >>= 1)
                acc[o] += __shfl_down_sync(0xffffffffu, acc[o], off);
        }
        if (lane == 0) {
            *(float4*)&g_proj[(long)row * PROJ_STRIDE] =
                make_float4(acc[0], acc[1], acc[2], acc[3]);
            g_proj[(long)row * PROJ_STRIDE + 4] = acc[4];
        }
    }
}

// ---------------------------------------------------------------------------
// Kernel 2: block-per-sample (grid 512). Each thread owns <=2 tokens,
// gathers 20 B proj rows, block-reduces 5 accumulators, computes the
// sample loss, then the last block computes the mean.
// ---------------------------------------------------------------------------
__global__ __launch_bounds__(256)
void loss_kernel(const int*   __restrict__ input_x,
                 const int*   __restrict__ lengths,
                 const int*   __restrict__ input_y,
                 const float* __restrict__ bias,
                 float*       __restrict__ out)
{
    __shared__ float s_red[8][OUTC];
    __shared__ float s_sum[256];
    __shared__ int   s_last;

    const int b    = blockIdx.x;
    const int tid  = threadIdx.x;
    const int wid  = tid >> 5;
    const int lane = tid & 31;
    const int len  = lengths[b];

    const int* xrow = input_x + b * SEQ;

    float acc[OUTC];
    #pragma unroll
    for (int o = 0; o < OUTC; o++) acc[o] = 0.f;

    // Token tid
    if (tid < len) {
        const int t = xrow[tid];
        float4 p = *(const float4*)&g_proj[(long)t * PROJ_STRIDE];
        float  q = g_proj[(long)t * PROJ_STRIDE + 4];
        acc[0] += p.x; acc[1] += p.y; acc[2] += p.z; acc[3] += p.w; acc[4] += q;
    }
    // Token tid + 256
    if (tid + 256 < len) {
        const int t = xrow[tid + 256];
        float4 p = *(const float4*)&g_proj[(long)t * PROJ_STRIDE];
        float  q = g_proj[(long)t * PROJ_STRIDE + 4];
        acc[0] += p.x; acc[1] += p.y; acc[2] += p.z; acc[3] += p.w; acc[4] += q;
    }

    // Warp reduction
    #pragma unroll
    for (int o = 0; o < OUTC; o++) {
        #pragma unroll
        for (int off = 16; off > 0; off >>= 1)
            acc[o] += __shfl_down_sync(0xffffffffu, acc[o], off);
    }
    if (lane == 0) {
        #pragma unroll
        for (int o = 0; o < OUTC; o++) s_red[wid][o] = acc[o];
    }
    __syncthreads();

    // Warp 0 combines the 8 warp partials and computes the loss
    if (tid == 0) {
        float tot[OUTC];
        #pragma unroll
        for (int o = 0; o < OUTC; o++) {
            tot[o] = ((s_red[0][o] + s_red[1][o]) + (s_red[2][o] + s_red[3][o]))
                   + ((s_red[4][o] + s_red[5][o]) + (s_red[6][o] + s_red[7][o]));
        }
        const float inv_len = 1.0f / (float)len;
        float logits[OUTC];
        float m = -INFINITY;
        #pragma unroll
        for (int o = 0; o < OUTC; o++) {
            logits[o] = tot[o] * inv_len + bias[o];
            m = fmaxf(m, logits[o]);
        }
        float se = 0.f;
        #pragma unroll
        for (int o = 0; o < OUTC; o++) se += __expf(logits[o] - m);
        const float lse = m + __logf(se);
        const int y = input_y[b];
        g_loss[b] = lse - logits[y];
        __threadfence();
        s_last = (atomicAdd(&g_count, 1u) == gridDim.x - 1) ? 1 : 0;
    }
    __syncthreads();

    // Last block: mean over 512 losses
    if (s_last) {
        __threadfence();
        s_sum[tid] = g_loss[tid] + g_loss[tid + 256];
        __syncthreads();
        #pragma unroll
        for (int off = 128; off > 0; off >>= 1) {
            if (tid < off) s_sum[tid] += s_sum[tid + off];
            __syncthreads();
        }
        if (tid == 0) {
            out[0] = s_sum[0] * (1.0f / (float)BATCH);
            g_count = 0;   // reset for next replay
        }
    }
}

extern "C" void kernel_launch(void* const* d_in, const int* in_sizes, int n_in,
                              void* d_out, int out_size)
{
    const int*   input_x = (const int*)d_in[0];
    const int*   lengths = (const int*)d_in[1];
    const int*   input_y = (const int*)d_in[2];
    const float* emb     = (const float*)d_in[3];
    const float* W       = (const float*)d_in[4];
    const float* bias    = (const float*)d_in[5];
    float* out = (float*)d_out;

    proj_kernel<<<592, 256>>>(emb, W);
    loss_kernel<<<BATCH, 256>>>(input_x, lengths, input_y, bias, out);
}